// round 3
// baseline (speedup 1.0000x reference)
#include <cuda_runtime.h>
#include <cstdint>
#include <math.h>

// 3 stacked dilated LSTM layers (rates 1,2,4), T=512, B=128, H=D=256, fp32.
// Grid: 16 gate-blocks x 8 batch-blocks = 128 co-resident CTAs (1/SM).
// 512 threads/CTA: 16 warps, warp = one 32-deep k-split; thread tile 8x4.

#define Hc    256
#define G4H   1024
#define BATCH 128
#define TT    512

#define WRS   516            // weight row stride (words): banks 4*r, conflict-free
#define URS   514            // u row stride (words): banks 2*n, conflict-free
#define PRS   20             // part row stride (words), float4-aligned
#define PPL   (64 * PRS)     // part plane stride
#define NPL   16             // # k-split planes

__device__ float    g_h[2][512 * 256];
__device__ float    g_c[512 * 256];
__device__ unsigned g_bar[8];

__device__ __forceinline__ unsigned long long fma2(unsigned long long a,
                                                   unsigned long long b,
                                                   unsigned long long c) {
    unsigned long long d;
    asm("fma.rn.f32x2 %0, %1, %2, %3;" : "=l"(d) : "l"(a), "l"(b), "l"(c));
    return d;
}

__device__ __forceinline__ float pairsum(unsigned long long v) {
    unsigned lo_, hi_;
    asm("mov.b64 {%0, %1}, %2;" : "=r"(lo_), "=r"(hi_) : "l"(v));
    return __uint_as_float(lo_) + __uint_as_float(hi_);
}

__device__ __forceinline__ void bar_arrive(unsigned* p) {
    asm volatile("red.release.gpu.global.add.u32 [%0], 1;" :: "l"(p) : "memory");
}
__device__ __forceinline__ unsigned bar_peek(unsigned* p) {
    unsigned v;
    asm volatile("ld.acquire.gpu.global.u32 %0, [%1];" : "=r"(v) : "l"(p) : "memory");
    return v;
}

__device__ __forceinline__ float sigmoidf_(float x) {
    return 1.0f / (1.0f + expf(-x));
}

extern "C" __global__ void __launch_bounds__(512, 1)
drnn_layer(const float* __restrict__ input,   // (T,128,256)
           const float* __restrict__ Wih,     // (L,1024,256)
           const float* __restrict__ Whh,     // (L,1024,256)
           const float* __restrict__ bih,     // (L,1024)
           const float* __restrict__ bhh,     // (L,1024)
           float* __restrict__ out,           // (L,512,128,256)
           int layer, int rate, int Td, int Nper, int nSub, unsigned barBase)
{
    extern __shared__ float sm[];
    float* w_s    = sm;                       // 64 x WRS
    float* pool   = w_s + 64 * WRS;           // u (16 x URS) aliased with part (16 x PPL)
    float* u_s    = pool;
    float* part   = pool;
    float* bias_s = pool + NPL * PPL;         // 64

    const int g   = blockIdx.x;
    const int nb  = blockIdx.y;
    const int tid = threadIdx.x;

    const float* WihL = Wih + (size_t)layer * G4H * Hc;
    const float* WhhL = Whh + (size_t)layer * G4H * Hc;

    // stationary weights: local row r = q*16+jl -> global row q*256 + g*16 + jl
    for (int idx = tid; idx < 64 * 512; idx += 512) {
        int r = idx >> 9;
        int k = idx & 511;
        int q  = r >> 4;
        int jl = r & 15;
        int R  = q * 256 + g * 16 + jl;
        float v = (k < 256) ? WihL[(size_t)R * 256 + k]
                            : WhhL[(size_t)R * 256 + (k - 256)];
        w_s[r * WRS + k] = v;
    }
    if (tid < 64) {
        int q = tid >> 4, jl = tid & 15;
        int R = q * 256 + g * 16 + jl;
        bias_s[tid] = bih[layer * G4H + R] + bhh[layer * G4H + R];
    }

    // thread roles
    const int kq   = tid >> 5;        // warp id = k-split 0..15 (k in [32kq, 32kq+32))
    const int lane = tid & 31;
    const int rg   = lane & 7;        // rows rg, rg+8, ..., rg+56
    const int cg   = lane >> 3;       // cols cg*4 .. cg*4+3
    const int pn   = tid >> 4;        // pointwise batch row (tid<256)
    const int pjl  = tid & 15;        // pointwise h-col

    const float* wp = w_s + rg * WRS + kq * 32;

    unsigned* barp = &g_bar[nb];

    for (int s = 0; s < Td; ++s) {
        const float* hprev = g_h[(s + 1) & 1];
        float* hcur = g_h[s & 1];

        for (int sub = 0; sub < nSub; ++sub) {
            const int nG0 = nb * Nper + sub * 16;

            __syncthreads();   // part consumed (or weights loaded) -> pool free

            // ---- fill u[n][k] = [x_t ; h_{s-1}]  (16 rows x 512 k)
            {
                int n  = tid >> 5;           // 0..15
                int l  = tid & 31;           // 0..31, k chunk l*16
                int nG = nG0 + n;
                int rr = nG >> 7;
                int bat = nG & 127;
                int time = s * rate + rr;
                int k0 = l * 16;
                float* ur = u_s + n * URS + k0;
                const float* src = (l < 16)
                    ? input + ((size_t)time * BATCH + bat) * Hc + k0
                    : hprev + (size_t)nG * Hc + (k0 - 256);
                #pragma unroll
                for (int i = 0; i < 16; i += 4) {
                    float4 v;
                    if (l >= 16 && s == 0) v = make_float4(0.f, 0.f, 0.f, 0.f);
                    else                   v = *(const float4*)(src + i);
                    *(float2*)(ur + i)     = make_float2(v.x, v.y);
                    *(float2*)(ur + i + 2) = make_float2(v.z, v.w);
                }
            }
            __syncthreads();

            // ---- microkernel: 8 rows x 4 cols per thread, depth 32 (16 k-pairs)
            unsigned long long acc[8][4];
            #pragma unroll
            for (int j = 0; j < 8; ++j)
                #pragma unroll
                for (int c = 0; c < 4; ++c) acc[j][c] = 0ULL;

            {
                const float* up = u_s + (cg * 4) * URS + kq * 32;
                #pragma unroll 4
                for (int kk = 0; kk < 32; kk += 2) {
                    unsigned long long uv[4], wv[8];
                    #pragma unroll
                    for (int c = 0; c < 4; ++c)
                        uv[c] = *(const unsigned long long*)(up + c * URS + kk);
                    #pragma unroll
                    for (int j = 0; j < 8; ++j)
                        wv[j] = *(const unsigned long long*)(wp + j * 8 * WRS + kk);
                    #pragma unroll
                    for (int j = 0; j < 8; ++j)
                        #pragma unroll
                        for (int c = 0; c < 4; ++c)
                            acc[j][c] = fma2(wv[j], uv[c], acc[j][c]);
                }
            }
            __syncthreads();   // all u reads done -> pool reusable as part

            // ---- write partials: plane kq, rows rg+8j, cols cg*4..cg*4+3
            {
                float* pp = part + kq * PPL + cg * 4;
                #pragma unroll
                for (int j = 0; j < 8; ++j) {
                    float4 v;
                    v.x = pairsum(acc[j][0]);
                    v.y = pairsum(acc[j][1]);
                    v.z = pairsum(acc[j][2]);
                    v.w = pairsum(acc[j][3]);
                    *(float4*)(pp + (rg + 8 * j) * PRS) = v;
                }
            }
            __syncthreads();

            // ---- pointwise LSTM update (256 threads: one (n, jl) each)
            if (tid < 256) {
                int n  = pn;
                int jl = pjl;
                int nG = nG0 + n;
                float gv[4];
                #pragma unroll
                for (int q = 0; q < 4; ++q) {
                    float v = bias_s[q * 16 + jl];
                    const float* pq = part + (q * 16 + jl) * PRS + n;
                    #pragma unroll
                    for (int sp = 0; sp < NPL; ++sp) v += pq[sp * PPL];
                    gv[q] = v;
                }
                float ig = sigmoidf_(gv[0]);
                float fg = sigmoidf_(gv[1]);
                float gt = tanhf(gv[2]);
                float og = sigmoidf_(gv[3]);

                int   jcol = g * 16 + jl;
                size_t sidx = (size_t)nG * Hc + jcol;
                float cold = (s == 0) ? 0.f : g_c[sidx];
                float cnew = fg * cold + ig * gt;
                float hnew = og * tanhf(cnew);
                g_c[sidx]  = cnew;
                hcur[sidx] = hnew;

                int rr   = nG >> 7;
                int bat  = nG & 127;
                int time = s * rate + rr;
                out[(((size_t)layer * TT + time) * BATCH + bat) * Hc + jcol] = hnew;
            }
        }

        // ---- barrier across the 16 gate-CTAs of this batch-block
        __threadfence();
        __syncthreads();
        if (tid == 0) {
            bar_arrive(barp);
            unsigned target = barBase + 16u * (unsigned)(s + 1);
            while (bar_peek(barp) < target) { }
        }
        __syncthreads();
    }
}

extern "C" void kernel_launch(void* const* d_in, const int* in_sizes, int n_in,
                              void* d_out, int out_size)
{
    const float* x   = (const float*)d_in[0];
    const float* Wih = (const float*)d_in[1];
    const float* Whh = (const float*)d_in[2];
    const float* bih = (const float*)d_in[3];
    const float* bhh = (const float*)d_in[4];
    float* out = (float*)d_out;

    const size_t smem = (size_t)(64 * WRS + NPL * PPL + 64) * sizeof(float);
    cudaFuncSetAttribute(drnn_layer, cudaFuncAttributeMaxDynamicSharedMemorySize, (int)smem);

    void* barp = nullptr;
    cudaGetSymbolAddress(&barp, g_bar);
    cudaMemsetAsync(barp, 0, 8 * sizeof(unsigned), 0);

    dim3 grid(16, 8);
    const size_t layer_elems = (size_t)TT * BATCH * Hc;

    drnn_layer<<<grid, 512, smem>>>(x, Wih, Whh, bih, bhh, out,
                                    0, 1, 512, 16, 1, 0u);
    drnn_layer<<<grid, 512, smem>>>(out, Wih, Whh, bih, bhh, out,
                                    1, 2, 256, 32, 2, 16u * 512u);
    drnn_layer<<<grid, 512, smem>>>(out + layer_elems, Wih, Whh, bih, bhh, out,
                                    2, 4, 128, 64, 4, 16u * 768u);
}

// round 4
// speedup vs baseline: 1.5177x; 1.5177x over previous
#include <cuda_runtime.h>
#include <cuda_bf16.h>
#include <cstdint>
#include <math.h>

// 3 stacked dilated LSTM layers (rates 1,2,4), T=512, B=128, H=D=256, fp32 I/O.
// Grid: 16 gate-blocks x 8 batch-blocks = 128 co-resident CTAs (1/SM).
// Microkernel: mma.sync m16n8k16 bf16, 2-term split (Whi*uhi + Whi*ulo + Wlo*uhi).
// Weights stay in registers as A-fragments for the whole kernel.

#define Hc    256
#define G4H   1024
#define BATCH 128
#define TT    512

#define URS2  520            // u row stride (bf16 elems): banks 4n+t, conflict-free
#define PRS   20             // part row stride (floats)
#define PPL   (64 * PRS)     // part plane stride
#define NPL   4              // k-split planes

__device__ float    g_h[2][512 * 256];
__device__ float    g_c[512 * 256];
__device__ unsigned g_bar[8];

__device__ __forceinline__ void bar_arrive(unsigned* p) {
    asm volatile("red.release.gpu.global.add.u32 [%0], 1;" :: "l"(p) : "memory");
}
__device__ __forceinline__ unsigned bar_peek(unsigned* p) {
    unsigned v;
    asm volatile("ld.acquire.gpu.global.u32 %0, [%1];" : "=r"(v) : "l"(p) : "memory");
    return v;
}
__device__ __forceinline__ float sigmoidf_(float x) {
    return 1.0f / (1.0f + expf(-x));
}

__device__ __forceinline__ void split_pack(float x, float y,
                                           unsigned& hi, unsigned& lo) {
    __nv_bfloat162 h2, l2;
    h2.x = __float2bfloat16(x);
    h2.y = __float2bfloat16(y);
    l2.x = __float2bfloat16(x - __bfloat162float(h2.x));
    l2.y = __float2bfloat16(y - __bfloat162float(h2.y));
    hi = *(unsigned*)&h2;
    lo = *(unsigned*)&l2;
}

__device__ __forceinline__ void mma16816(float d[4], const unsigned a[4],
                                         unsigned b0, unsigned b1) {
    asm volatile(
        "mma.sync.aligned.m16n8k16.row.col.f32.bf16.bf16.f32 "
        "{%0,%1,%2,%3},{%4,%5,%6,%7},{%8,%9},{%0,%1,%2,%3};"
        : "+f"(d[0]), "+f"(d[1]), "+f"(d[2]), "+f"(d[3])
        : "r"(a[0]), "r"(a[1]), "r"(a[2]), "r"(a[3]), "r"(b0), "r"(b1));
}

extern "C" __global__ void __launch_bounds__(512, 1)
drnn_layer(const float* __restrict__ input,   // (T,128,256)
           const float* __restrict__ Wih,     // (L,1024,256)
           const float* __restrict__ Whh,     // (L,1024,256)
           const float* __restrict__ bih,     // (L,1024)
           const float* __restrict__ bhh,     // (L,1024)
           float* __restrict__ out,           // (L,512,128,256)
           int layer, int rate, int Td, int Nper, int nSub, unsigned barBase)
{
    extern __shared__ char smraw[];
    unsigned short* u_hi = (unsigned short*)smraw;          // 16 x URS2 bf16
    unsigned short* u_lo = u_hi + 16 * URS2;                // 16 x URS2 bf16
    float* part   = (float*)(smraw + (size_t)2 * 16 * URS2 * 2);  // NPL x PPL
    float* bias_s = part + NPL * PPL;                       // 64

    const int g   = blockIdx.x;
    const int nb  = blockIdx.y;
    const int tid = threadIdx.x;

    const float* WihL = Wih + (size_t)layer * G4H * Hc;
    const float* WhhL = Whh + (size_t)layer * G4H * Hc;

    // warp roles: 16 warps = 4 gate-tiles (q) x 4 k-splits (ks)
    const int wid  = tid >> 5;
    const int lane = tid & 31;
    const int q    = wid & 3;         // gate quadrant (16 gate rows)
    const int ks   = wid >> 2;        // k-split: k in [128*ks, 128*ks+128)
    const int gid  = lane >> 2;       // 0..7
    const int t4   = lane & 3;        // 0..3

    // ---- build stationary A fragments (Whi, Wlo) in registers
    // local gate row m = q*16 + jl  <->  global row q*256 + g*16 + jl
    unsigned a_hi[8][4], a_lo[8][4];
    {
        const int rowT = q * 256 + g * 16 + gid;     // rows for a0/a2
        const int rowB = rowT + 8;                   // rows for a1/a3
        #pragma unroll
        for (int i = 0; i < 8; ++i) {
            int kt = ks * 8 + i;
            int kb = kt * 16 + t4 * 2;               // k element for a0/a1
            #pragma unroll
            for (int r = 0; r < 4; ++r) {
                int row = (r & 1) ? rowB : rowT;
                int k   = kb + ((r >> 1) ? 8 : 0);
                const float* src = (k < 256)
                    ? WihL + (size_t)row * Hc + k
                    : WhhL + (size_t)row * Hc + (k - 256);
                float2 v = *(const float2*)src;
                split_pack(v.x, v.y, a_hi[i][r], a_lo[i][r]);
            }
        }
    }
    if (tid < 64) {
        int qq = tid >> 4, jl = tid & 15;
        int R = qq * 256 + g * 16 + jl;
        bias_s[tid] = bih[layer * G4H + R] + bhh[layer * G4H + R];
    }

    const int pn  = tid >> 4;     // pointwise batch row (tid < 256)
    const int pjl = tid & 15;     // pointwise h-col

    unsigned* barp = &g_bar[nb];

    for (int s = 0; s < Td; ++s) {
        const float* hprev = g_h[(s + 1) & 1];
        float* hcur = g_h[s & 1];

        for (int sub = 0; sub < nSub; ++sub) {
            const int nG0 = nb * Nper + sub * 16;

            __syncthreads();   // prev pointwise done; u / part writable

            // ---- fill u = [x_t ; h_{s-1}] as bf16 hi/lo, n-major
            {
                int n  = tid >> 5;           // 0..15
                int l  = tid & 31;           // 0..31 -> k chunk l*16
                int nG = nG0 + n;
                int rr = nG >> 7;
                int bat = nG & 127;
                int time = s * rate + rr;
                int k0 = l * 16;
                bool zero = (l >= 16) && (s == 0);
                const float* src = (l < 16)
                    ? input + ((size_t)time * BATCH + bat) * Hc + k0
                    : hprev + (size_t)nG * Hc + (k0 - 256);
                unsigned* dh = (unsigned*)(u_hi + n * URS2 + k0);
                unsigned* dl = (unsigned*)(u_lo + n * URS2 + k0);
                #pragma unroll
                for (int i = 0; i < 8; ++i) {
                    float2 v = zero ? make_float2(0.f, 0.f)
                                    : ((const float2*)src)[i];
                    unsigned ph, pl;
                    split_pack(v.x, v.y, ph, pl);
                    dh[i] = ph;
                    dl[i] = pl;
                }
            }
            __syncthreads();

            // ---- HMMA microkernel: warp tile 16(gate) x 16(batch), 8 k-tiles
            {
                float d0[4] = {0.f, 0.f, 0.f, 0.f};   // batch cols 0..7
                float d1[4] = {0.f, 0.f, 0.f, 0.f};   // batch cols 8..15

                #pragma unroll
                for (int i = 0; i < 8; ++i) {
                    int kof = (ks * 8 + i) * 16 + t4 * 2;   // bf16 elem index
                    const unsigned* uh0 = (const unsigned*)(u_hi + gid * URS2 + kof);
                    const unsigned* ul0 = (const unsigned*)(u_lo + gid * URS2 + kof);
                    const unsigned* uh8 = (const unsigned*)(u_hi + (gid + 8) * URS2 + kof);
                    const unsigned* ul8 = (const unsigned*)(u_lo + (gid + 8) * URS2 + kof);
                    unsigned bh0a = uh0[0], bh0b = uh0[4];   // +4 uints = +8 elems
                    unsigned bl0a = ul0[0], bl0b = ul0[4];
                    unsigned bh8a = uh8[0], bh8b = uh8[4];
                    unsigned bl8a = ul8[0], bl8b = ul8[4];

                    mma16816(d0, a_hi[i], bh0a, bh0b);
                    mma16816(d0, a_hi[i], bl0a, bl0b);
                    mma16816(d0, a_lo[i], bh0a, bh0b);
                    mma16816(d1, a_hi[i], bh8a, bh8b);
                    mma16816(d1, a_hi[i], bl8a, bl8b);
                    mma16816(d1, a_lo[i], bh8a, bh8b);
                }

                // D frag: rows gid/gid+8 (jl), cols 2*t4(+1), plane = ks
                float* pp = part + ks * PPL + (q * 16) * PRS;
                *(float2*)(pp + gid * PRS + 2 * t4)            = make_float2(d0[0], d0[1]);
                *(float2*)(pp + (gid + 8) * PRS + 2 * t4)      = make_float2(d0[2], d0[3]);
                *(float2*)(pp + gid * PRS + 8 + 2 * t4)        = make_float2(d1[0], d1[1]);
                *(float2*)(pp + (gid + 8) * PRS + 8 + 2 * t4)  = make_float2(d1[2], d1[3]);
            }
            __syncthreads();

            // ---- pointwise LSTM update (256 threads)
            if (tid < 256) {
                int n  = pn;
                int jl = pjl;
                int nG = nG0 + n;
                float gv[4];
                #pragma unroll
                for (int qq = 0; qq < 4; ++qq) {
                    float v = bias_s[qq * 16 + jl];
                    const float* pq = part + (qq * 16 + jl) * PRS + n;
                    #pragma unroll
                    for (int sp = 0; sp < NPL; ++sp) v += pq[sp * PPL];
                    gv[qq] = v;
                }
                float ig = sigmoidf_(gv[0]);
                float fg = sigmoidf_(gv[1]);
                float gt = tanhf(gv[2]);
                float og = sigmoidf_(gv[3]);

                int   jcol = g * 16 + jl;
                size_t sidx = (size_t)nG * Hc + jcol;
                float cold = (s == 0) ? 0.f : g_c[sidx];
                float cnew = fg * cold + ig * gt;
                float hnew = og * tanhf(cnew);
                g_c[sidx]  = cnew;
                hcur[sidx] = hnew;

                int rr   = nG >> 7;
                int bat  = nG & 127;
                int time = s * rate + rr;
                out[(((size_t)layer * TT + time) * BATCH + bat) * Hc + jcol] = hnew;
            }
        }

        // ---- barrier across the 16 gate-CTAs of this batch-block
        __threadfence();
        __syncthreads();
        if (tid == 0) {
            bar_arrive(barp);
            unsigned target = barBase + 16u * (unsigned)(s + 1);
            while (bar_peek(barp) < target) { }
        }
        __syncthreads();
    }
}

extern "C" void kernel_launch(void* const* d_in, const int* in_sizes, int n_in,
                              void* d_out, int out_size)
{
    const float* x   = (const float*)d_in[0];
    const float* Wih = (const float*)d_in[1];
    const float* Whh = (const float*)d_in[2];
    const float* bih = (const float*)d_in[3];
    const float* bhh = (const float*)d_in[4];
    float* out = (float*)d_out;

    const size_t smem = (size_t)2 * 16 * URS2 * 2          // u hi/lo bf16
                      + (size_t)(NPL * PPL + 64) * sizeof(float);
    cudaFuncSetAttribute(drnn_layer, cudaFuncAttributeMaxDynamicSharedMemorySize, (int)smem);

    void* barp = nullptr;
    cudaGetSymbolAddress(&barp, g_bar);
    cudaMemsetAsync(barp, 0, 8 * sizeof(unsigned), 0);

    dim3 grid(16, 8);
    const size_t layer_elems = (size_t)TT * BATCH * Hc;

    drnn_layer<<<grid, 512, smem>>>(x, Wih, Whh, bih, bhh, out,
                                    0, 1, 512, 16, 1, 0u);
    drnn_layer<<<grid, 512, smem>>>(out, Wih, Whh, bih, bhh, out,
                                    1, 2, 256, 32, 2, 16u * 512u);
    drnn_layer<<<grid, 512, smem>>>(out + layer_elems, Wih, Whh, bih, bhh, out,
                                    2, 4, 128, 64, 4, 16u * 768u);
}

// round 5
// speedup vs baseline: 2.4431x; 1.6098x over previous
#include <cuda_runtime.h>
#include <cuda_bf16.h>
#include <cstdint>
#include <math.h>

// 3 stacked dilated LSTM layers (rates 1,2,4), T=512, B=128, H=D=256, fp32 I/O.
// Phase A (per layer): gx = X @ Wih^T + bih + bhh  -- big parallel HMMA GEMM.
// Phase B (per layer): recurrent scan, gates = gx + h @ Whh^T, 16x8 CTAs,
//   HMMA bf16 2-term split, h exchanged pre-split (bf16 hi/lo) via global mem.

#define Hc    256
#define BATCH 128
#define TT    512

#define URS2  264            // u row stride (bf16 elems)
#define PRS   68             // part row stride (floats)
#define PPL   (64 * PRS)
#define GXS   72             // GEMM smem k-stride (shorts)

__device__ float          g_gx[(size_t)TT * BATCH * 1024];   // 256 MB scratch
__device__ unsigned short g_hh[2][512 * 256];                // h hi plane (bf16)
__device__ unsigned short g_hl[2][512 * 256];                // h lo plane (bf16)
__device__ float          g_c[512 * 256];
__device__ unsigned       g_bar[8];

__device__ __forceinline__ void bar_arrive(unsigned* p) {
    asm volatile("red.release.gpu.global.add.u32 [%0], 1;" :: "l"(p) : "memory");
}
__device__ __forceinline__ unsigned bar_peek(unsigned* p) {
    unsigned v;
    asm volatile("ld.acquire.gpu.global.u32 %0, [%1];" : "=r"(v) : "l"(p) : "memory");
    return v;
}
__device__ __forceinline__ float sigmoidf_(float x) {
    return 1.0f / (1.0f + expf(-x));
}
__device__ __forceinline__ void split_pack(float x, float y,
                                           unsigned& hi, unsigned& lo) {
    __nv_bfloat162 h2, l2;
    h2.x = __float2bfloat16(x);
    h2.y = __float2bfloat16(y);
    l2.x = __float2bfloat16(x - __bfloat162float(h2.x));
    l2.y = __float2bfloat16(y - __bfloat162float(h2.y));
    hi = *(unsigned*)&h2;
    lo = *(unsigned*)&l2;
}
__device__ __forceinline__ void mma16816(float d[4], const unsigned a[4],
                                         unsigned b0, unsigned b1) {
    asm volatile(
        "mma.sync.aligned.m16n8k16.row.col.f32.bf16.bf16.f32 "
        "{%0,%1,%2,%3},{%4,%5,%6,%7},{%8,%9},{%0,%1,%2,%3};"
        : "+f"(d[0]), "+f"(d[1]), "+f"(d[2]), "+f"(d[3])
        : "r"(a[0]), "r"(a[1]), "r"(a[2]), "r"(a[3]), "r"(b0), "r"(b1));
}

// ============================================================================
// Phase A: gx[row, R] = sum_k X[row,k] * W[R,k] + b1[R] + b2[R]
// grid (8, 512): bn over 1024 gate rows /128, bm over 65536 x-rows /128.
// ============================================================================
extern "C" __global__ void __launch_bounds__(512, 1)
gemm_gx(const float* __restrict__ X,      // (65536, 256)
        const float* __restrict__ W,      // (1024, 256)
        const float* __restrict__ b1,
        const float* __restrict__ b2)
{
    extern __shared__ char sm[];
    unsigned short* Xh = (unsigned short*)sm;        // 128 x GXS
    unsigned short* Xl = Xh + 128 * GXS;
    unsigned short* Wh = Xl + 128 * GXS;
    unsigned short* Wl = Wh + 128 * GXS;
    float* bias_s = (float*)(Wl + 128 * GXS);        // 128

    const int bn = blockIdx.x, bm = blockIdx.y;
    const int tid  = threadIdx.x;
    const int wid  = tid >> 5, lane = tid & 31;
    const int wm   = wid >> 2, wn = wid & 3;         // warp tile 32x32
    const int gid  = lane >> 2, t4 = lane & 3;

    if (tid < 128) bias_s[tid] = b1[bn * 128 + tid] + b2[bn * 128 + tid];

    float dd[2][4][4];
    #pragma unroll
    for (int mt = 0; mt < 2; ++mt)
        #pragma unroll
        for (int nt = 0; nt < 4; ++nt)
            #pragma unroll
            for (int r = 0; r < 4; ++r) dd[mt][nt][r] = 0.f;

    const int r_ld = tid >> 2;
    const int p_ld = tid & 3;

    for (int kp = 0; kp < 4; ++kp) {
        __syncthreads();
        #pragma unroll
        for (int i = 0; i < 4; ++i) {
            int kl  = (p_ld * 4 + i) * 4;            // 0..60
            int kgl = kp * 64 + kl;
            float4 xv = *(const float4*)(X + ((size_t)(bm * 128 + r_ld)) * 256 + kgl);
            float4 wv = *(const float4*)(W + ((size_t)(bn * 128 + r_ld)) * 256 + kgl);
            unsigned h0, l0, h1, l1;
            split_pack(xv.x, xv.y, h0, l0);
            split_pack(xv.z, xv.w, h1, l1);
            *(unsigned*)(Xh + r_ld * GXS + kl)     = h0;
            *(unsigned*)(Xh + r_ld * GXS + kl + 2) = h1;
            *(unsigned*)(Xl + r_ld * GXS + kl)     = l0;
            *(unsigned*)(Xl + r_ld * GXS + kl + 2) = l1;
            split_pack(wv.x, wv.y, h0, l0);
            split_pack(wv.z, wv.w, h1, l1);
            *(unsigned*)(Wh + r_ld * GXS + kl)     = h0;
            *(unsigned*)(Wh + r_ld * GXS + kl + 2) = h1;
            *(unsigned*)(Wl + r_ld * GXS + kl)     = l0;
            *(unsigned*)(Wl + r_ld * GXS + kl + 2) = l1;
        }
        __syncthreads();

        #pragma unroll
        for (int i = 0; i < 4; ++i) {
            int k0 = i * 16 + t4 * 2;
            unsigned ah[2][4], al[2][4];
            #pragma unroll
            for (int mt = 0; mt < 2; ++mt) {
                int r0 = wm * 32 + mt * 16;
                ah[mt][0] = *(unsigned*)(Xh + (r0 + gid)     * GXS + k0);
                ah[mt][1] = *(unsigned*)(Xh + (r0 + gid + 8) * GXS + k0);
                ah[mt][2] = *(unsigned*)(Xh + (r0 + gid)     * GXS + k0 + 8);
                ah[mt][3] = *(unsigned*)(Xh + (r0 + gid + 8) * GXS + k0 + 8);
                al[mt][0] = *(unsigned*)(Xl + (r0 + gid)     * GXS + k0);
                al[mt][1] = *(unsigned*)(Xl + (r0 + gid + 8) * GXS + k0);
                al[mt][2] = *(unsigned*)(Xl + (r0 + gid)     * GXS + k0 + 8);
                al[mt][3] = *(unsigned*)(Xl + (r0 + gid + 8) * GXS + k0 + 8);
            }
            #pragma unroll
            for (int nt = 0; nt < 4; ++nt) {
                int n0 = wn * 32 + nt * 8;
                unsigned bh0 = *(unsigned*)(Wh + (n0 + gid) * GXS + k0);
                unsigned bh1 = *(unsigned*)(Wh + (n0 + gid) * GXS + k0 + 8);
                unsigned bl0 = *(unsigned*)(Wl + (n0 + gid) * GXS + k0);
                unsigned bl1 = *(unsigned*)(Wl + (n0 + gid) * GXS + k0 + 8);
                #pragma unroll
                for (int mt = 0; mt < 2; ++mt) {
                    mma16816(dd[mt][nt], ah[mt], bh0, bh1);
                    mma16816(dd[mt][nt], ah[mt], bl0, bl1);
                    mma16816(dd[mt][nt], al[mt], bh0, bh1);
                }
            }
        }
    }
    __syncthreads();

    #pragma unroll
    for (int mt = 0; mt < 2; ++mt)
        #pragma unroll
        for (int nt = 0; nt < 4; ++nt) {
            int rowA = bm * 128 + wm * 32 + mt * 16 + gid;
            int cl   = wn * 32 + nt * 8 + 2 * t4;
            int col  = bn * 128 + cl;
            float bx = bias_s[cl], by = bias_s[cl + 1];
            *(float2*)(g_gx + (size_t)rowA * 1024 + col) =
                make_float2(dd[mt][nt][0] + bx, dd[mt][nt][1] + by);
            *(float2*)(g_gx + (size_t)(rowA + 8) * 1024 + col) =
                make_float2(dd[mt][nt][2] + bx, dd[mt][nt][3] + by);
        }
}

// ============================================================================
// Phase B: recurrent scan. grid (16 gate-CTAs, 8 batch-blocks).
// NT16 = Nper/16 (1,2,4 for layers 0,1,2).
// ============================================================================
template<int NT16>
__global__ void __launch_bounds__(512, 1)
recur(const float* __restrict__ WhhL,     // this layer's (1024,256)
      float* __restrict__ out,
      int layer, int rate, int Td, unsigned barBase)
{
    constexpr int Nper = NT16 * 16;
    constexpr int REPS = (NT16 * 256 + 511) / 512;

    extern __shared__ char smraw[];
    unsigned short* u_hi = (unsigned short*)smraw;        // 64 x URS2
    unsigned short* u_lo = u_hi + 64 * URS2;
    float* part = (float*)(smraw + (size_t)2 * 64 * URS2 * 2);  // 4 x PPL

    const int g   = blockIdx.x;
    const int nb  = blockIdx.y;
    const int tid = threadIdx.x;
    const int wid = tid >> 5, lane = tid & 31;
    const int q   = wid & 3;          // gate quadrant
    const int ks  = wid >> 2;         // k-split (64 k each)
    const int gid = lane >> 2, t4 = lane & 3;

    // stationary A fragments from Whh (K = 256)
    unsigned a_hi[4][4], a_lo[4][4];
    {
        const int rowT = q * 256 + g * 16 + gid;
        const int rowB = rowT + 8;
        #pragma unroll
        for (int i = 0; i < 4; ++i) {
            int kb = (ks * 4 + i) * 16 + t4 * 2;
            #pragma unroll
            for (int r = 0; r < 4; ++r) {
                int row = (r & 1) ? rowB : rowT;
                int k   = kb + ((r >> 1) ? 8 : 0);
                float2 v = *(const float2*)(WhhL + (size_t)row * 256 + k);
                split_pack(v.x, v.y, a_hi[i][r], a_lo[i][r]);
            }
        }
    }

    unsigned* barp = &g_bar[nb];

    // gx prefetch for step 0
    float gxp[REPS][4];
    #pragma unroll
    for (int rep = 0; rep < REPS; ++rep) {
        int e = tid + 512 * rep;
        if (e < NT16 * 256) {
            int n = e >> 4, jl = e & 15;
            int nG = nb * Nper + n;
            int rr = nG >> 7, bat = nG & 127;
            int time = 0 * rate + rr;
            const float* gp = g_gx + ((size_t)(time * BATCH + bat)) * 1024 + g * 16 + jl;
            #pragma unroll
            for (int qq = 0; qq < 4; ++qq) gxp[rep][qq] = gp[qq * 256];
        }
    }

    for (int s = 0; s < Td; ++s) {
        // ---- fill u = h_{s-1} (pre-split bf16 hi/lo)
        {
            const unsigned short* shh = g_hh[(s + 1) & 1];
            const unsigned short* shl = g_hl[(s + 1) & 1];
            #pragma unroll
            for (int it = 0; it < NT16; ++it) {
                int idx = tid + 512 * it;            // < NT16*512
                int n  = idx >> 5;
                int k0 = (idx & 31) * 8;
                int nG = nb * Nper + n;
                uint4 vh, vl;
                if (s == 0) {
                    vh = make_uint4(0, 0, 0, 0);
                    vl = vh;
                } else {
                    vh = *(const uint4*)(shh + (size_t)nG * 256 + k0);
                    vl = *(const uint4*)(shl + (size_t)nG * 256 + k0);
                }
                *(uint4*)(u_hi + n * URS2 + k0) = vh;
                *(uint4*)(u_lo + n * URS2 + k0) = vl;
            }
        }
        __syncthreads();

        // ---- HMMA: gates_part = h @ Whh^T (split x3)
        {
            float dd[NT16][8];
            #pragma unroll
            for (int nt = 0; nt < NT16; ++nt)
                #pragma unroll
                for (int r = 0; r < 8; ++r) dd[nt][r] = 0.f;

            #pragma unroll
            for (int i = 0; i < 4; ++i) {
                int kof = (ks * 4 + i) * 16 + t4 * 2;
                #pragma unroll
                for (int nt = 0; nt < NT16; ++nt) {
                    const unsigned short* uh = u_hi + (nt * 16 + gid) * URS2 + kof;
                    const unsigned short* ul = u_lo + (nt * 16 + gid) * URS2 + kof;
                    unsigned bh0a = *(const unsigned*)uh;
                    unsigned bh0b = *(const unsigned*)(uh + 8);
                    unsigned bl0a = *(const unsigned*)ul;
                    unsigned bl0b = *(const unsigned*)(ul + 8);
                    unsigned bh8a = *(const unsigned*)(uh + 8 * URS2);
                    unsigned bh8b = *(const unsigned*)(uh + 8 * URS2 + 8);
                    unsigned bl8a = *(const unsigned*)(ul + 8 * URS2);
                    unsigned bl8b = *(const unsigned*)(ul + 8 * URS2 + 8);
                    mma16816(dd[nt] + 0, a_hi[i], bh0a, bh0b);
                    mma16816(dd[nt] + 0, a_hi[i], bl0a, bl0b);
                    mma16816(dd[nt] + 0, a_lo[i], bh0a, bh0b);
                    mma16816(dd[nt] + 4, a_hi[i], bh8a, bh8b);
                    mma16816(dd[nt] + 4, a_hi[i], bl8a, bl8b);
                    mma16816(dd[nt] + 4, a_lo[i], bh8a, bh8b);
                }
            }

            #pragma unroll
            for (int nt = 0; nt < NT16; ++nt) {
                float* pp = part + ks * PPL + (q * 16) * PRS + nt * 16;
                *(float2*)(pp + gid * PRS + 2 * t4)           = make_float2(dd[nt][0], dd[nt][1]);
                *(float2*)(pp + (gid + 8) * PRS + 2 * t4)     = make_float2(dd[nt][2], dd[nt][3]);
                *(float2*)(pp + gid * PRS + 8 + 2 * t4)       = make_float2(dd[nt][4], dd[nt][5]);
                *(float2*)(pp + (gid + 8) * PRS + 8 + 2 * t4) = make_float2(dd[nt][6], dd[nt][7]);
            }
        }
        __syncthreads();

        // ---- pointwise: compute h, store pre-split h FIRST
        float hsv[REPS], csv[REPS];
        {
            unsigned short* dhh = g_hh[s & 1];
            unsigned short* dhl = g_hl[s & 1];
            #pragma unroll
            for (int rep = 0; rep < REPS; ++rep) {
                int e = tid + 512 * rep;
                if (e < NT16 * 256) {
                    int n = e >> 4, jl = e & 15;
                    int nG = nb * Nper + n;
                    float gv[4];
                    #pragma unroll
                    for (int qq = 0; qq < 4; ++qq) {
                        float v = gxp[rep][qq];
                        const float* pq = part + (qq * 16 + jl) * PRS + n;
                        #pragma unroll
                        for (int sp = 0; sp < 4; ++sp) v += pq[sp * PPL];
                        gv[qq] = v;
                    }
                    float ig = sigmoidf_(gv[0]);
                    float fg = sigmoidf_(gv[1]);
                    float gt = tanhf(gv[2]);
                    float og = sigmoidf_(gv[3]);

                    int jcol = g * 16 + jl;
                    size_t sidx = (size_t)nG * 256 + jcol;
                    float cold = (s == 0) ? 0.f : g_c[sidx];
                    float cnew = fg * cold + ig * gt;
                    float hnew = og * tanhf(cnew);
                    csv[rep] = cnew;
                    hsv[rep] = hnew;

                    __nv_bfloat16 hh = __float2bfloat16(hnew);
                    __nv_bfloat16 hl = __float2bfloat16(hnew - __bfloat162float(hh));
                    dhh[sidx] = *(unsigned short*)&hh;
                    dhl[sidx] = *(unsigned short*)&hl;
                }
            }
        }
        __syncthreads();
        if (tid == 0) bar_arrive(barp);

        // ---- hidden behind barrier: c/out stores + next-step gx prefetch
        #pragma unroll
        for (int rep = 0; rep < REPS; ++rep) {
            int e = tid + 512 * rep;
            if (e < NT16 * 256) {
                int n = e >> 4, jl = e & 15;
                int nG = nb * Nper + n;
                int rr = nG >> 7, bat = nG & 127;
                int time = s * rate + rr;
                int jcol = g * 16 + jl;
                g_c[(size_t)nG * 256 + jcol] = csv[rep];
                out[((size_t)(layer * TT + time) * BATCH + bat) * Hc + jcol] = hsv[rep];
                if (s + 1 < Td) {
                    int time2 = (s + 1) * rate + rr;
                    const float* gp = g_gx + ((size_t)(time2 * BATCH + bat)) * 1024 + g * 16 + jl;
                    #pragma unroll
                    for (int qq = 0; qq < 4; ++qq) gxp[rep][qq] = gp[qq * 256];
                }
            }
        }

        if (tid == 0) {
            unsigned target = barBase + 16u * (unsigned)(s + 1);
            while (bar_peek(barp) < target) { }
        }
        __syncthreads();
    }
}

extern "C" void kernel_launch(void* const* d_in, const int* in_sizes, int n_in,
                              void* d_out, int out_size)
{
    const float* x   = (const float*)d_in[0];
    const float* Wih = (const float*)d_in[1];
    const float* Whh = (const float*)d_in[2];
    const float* bih = (const float*)d_in[3];
    const float* bhh = (const float*)d_in[4];
    float* out = (float*)d_out;

    const int gsm = 4 * 128 * GXS * 2 + 128 * 4;                       // 74,240
    const int rsm = 2 * 64 * URS2 * 2 + 4 * PPL * 4;                   // 137,216
    cudaFuncSetAttribute(gemm_gx, cudaFuncAttributeMaxDynamicSharedMemorySize, gsm);
    cudaFuncSetAttribute(recur<1>, cudaFuncAttributeMaxDynamicSharedMemorySize, rsm);
    cudaFuncSetAttribute(recur<2>, cudaFuncAttributeMaxDynamicSharedMemorySize, rsm);
    cudaFuncSetAttribute(recur<4>, cudaFuncAttributeMaxDynamicSharedMemorySize, rsm);

    void* barp = nullptr;
    cudaGetSymbolAddress(&barp, g_bar);
    cudaMemsetAsync(barp, 0, 8 * sizeof(unsigned), 0);

    const size_t le = (size_t)TT * BATCH * Hc;
    dim3 ggrid(8, 512), rgrid(16, 8);

    // layer 0
    gemm_gx<<<ggrid, 512, gsm>>>(x, Wih, bih, bhh);
    recur<1><<<rgrid, 512, rsm>>>(Whh, out, 0, 1, 512, 0u);
    // layer 1
    gemm_gx<<<ggrid, 512, gsm>>>(out, Wih + 1024 * 256, bih + 1024, bhh + 1024);
    recur<2><<<rgrid, 512, rsm>>>(Whh + 1024 * 256, out, 1, 2, 256, 16u * 512u);
    // layer 2
    gemm_gx<<<ggrid, 512, gsm>>>(out + le, Wih + 2 * 1024 * 256, bih + 2048, bhh + 2048);
    recur<4><<<rgrid, 512, rsm>>>(Whh + 2 * 1024 * 256, out, 2, 4, 128, 16u * 768u);
}